// round 17
// baseline (speedup 1.0000x reference)
#include <cuda_runtime.h>
#include <stdint.h>

#define BB 4
#define NN 16384
#define SS 4096
#define KK 16
#define PP 64
#define QQ 128
#define CLUS 8

#define OUT_SHAPES 0
#define OUT_XYZ (BB * QQ * SS)              // 2097152
#define OUT_IDX (OUT_XYZ + BB * SS * 3)     // 2146304

__device__ float g_centers[BB * SS * 3];
__device__ int   g_knn[BB * SS * KK];

__device__ __forceinline__ float finf() { return __int_as_float(0x7f800000); }

// ---- packed f32x2 helpers (per-lane rn fp32: bit-identical to scalar) ----
__device__ __forceinline__ uint64_t pack2(float a, float b) {
    uint64_t r; asm("mov.b64 %0, {%1, %2};" : "=l"(r) : "f"(a), "f"(b)); return r;
}
__device__ __forceinline__ void unpack2(uint64_t v, float& a, float& b) {
    asm("mov.b64 {%0, %1}, %2;" : "=f"(a), "=f"(b) : "l"(v));
}
__device__ __forceinline__ uint64_t add2(uint64_t a, uint64_t b) {
    uint64_t r; asm("add.rn.f32x2 %0, %1, %2;" : "=l"(r) : "l"(a), "l"(b)); return r;
}
__device__ __forceinline__ uint64_t mul2(uint64_t a, uint64_t b) {
    uint64_t r; asm("mul.rn.f32x2 %0, %1, %2;" : "=l"(r) : "l"(a), "l"(b)); return r;
}

// d = ((dx*dx)+(dy*dy))+(dz*dz) per packed lane; dx = x + (-cx) == x - cx exactly.
__device__ __forceinline__ void upd(uint64_t X, uint64_t Y, uint64_t Z,
                                    uint64_t ncx, uint64_t ncy, uint64_t ncz,
                                    float& d0, float& d1) {
    uint64_t dx = add2(X, ncx); dx = mul2(dx, dx);
    uint64_t dy = add2(Y, ncy); dy = mul2(dy, dy);
    uint64_t dz = add2(Z, ncz); dz = mul2(dz, dz);
    uint64_t s = add2(add2(dx, dy), dz);
    float a, b; unpack2(s, a, b);
    d0 = fminf(d0, a);
    d1 = fminf(d1, b);
}

__device__ __forceinline__ unsigned smem_u32(const void* p) {
    return (unsigned)__cvta_generic_to_shared(p);
}
__device__ __forceinline__ unsigned mapa_u32(unsigned laddr, unsigned rank) {
    unsigned r;
    asm("mapa.shared::cluster.u32 %0, %1, %2;" : "=r"(r) : "r"(laddr), "r"(rank));
    return r;
}

#define MBAR_INIT(laddr, cnt) \
    asm volatile("mbarrier.init.shared.b64 [%0], %1;" :: "r"(laddr), "r"(cnt) : "memory")

// Arm next phase: one arrive (count=1) + expect 512 tx bytes (64 keys x 8B).
#define MBAR_ARRIVE_EXPECT_TX(laddr, bytes) \
    asm volatile("mbarrier.arrive.expect_tx.shared.b64 _, [%0], %1;" \
                 :: "r"(laddr), "r"(bytes) : "memory")

#define CLUSTER_SYNC_() do { \
    asm volatile("barrier.cluster.arrive.aligned;" ::: "memory"); \
    asm volatile("barrier.cluster.wait.aligned;" ::: "memory"); } while (0)

// Fused remote store + completion: data delivery decrements the remote mbar's
// tx-count — no separate arrive hop, no pre-send bar.sync needed.
#define ST_ASYNC_U64(raddr, val, rmbar) \
    asm volatile("st.async.weak.shared::cluster.mbarrier::complete_tx::bytes.u64 [%0], %1, [%2];" \
                 :: "r"(raddr), "l"(val), "r"(rmbar) : "memory")

// Parity wait with cluster-scope acquire (makes remote async stores visible).
#define MBAR_WAIT_PARITY_CLUSTER(laddr, par) do {                              \
    asm volatile(                                                              \
        "{\n\t.reg .pred P1;\n\t"                                              \
        "WL_%=:\n\t"                                                           \
        "mbarrier.try_wait.parity.acquire.cluster.shared::cta.b64 P1, [%0], %1, 0x989680;\n\t" \
        "@P1 bra WD_%=;\n\t"                                                   \
        "bra WL_%=;\n\t"                                                       \
        "WD_%=:\n\t}"                                                          \
        :: "r"(laddr), "r"(par) : "memory");                                   \
} while (0)

// ---------------------------------------------------------------------------
// Kernel 1: cluster-parallel FPS (BYTE-IDENTICAL to the R16 winner).
// ---------------------------------------------------------------------------
__global__ __launch_bounds__(256, 1) __cluster_dims__(CLUS, 1, 1)
void fps_kernel(const float* __restrict__ xyz, float* __restrict__ out)
{
    extern __shared__ float smf[];
    float* sx = smf;
    float* sy = smf + NN;
    float* sz = smf + 2 * NN;
    __shared__ unsigned long long s_slots[2][CLUS * 8];   // [parity][srcCTA*8+srcWarp]
    __shared__ unsigned long long s_mbar[2];

    const int tid = threadIdx.x;
    const int wid = tid >> 5, lane = tid & 31;
    unsigned rank;
    asm("mov.u32 %0, %%cluster_ctarank;" : "=r"(rank));
    const int b = blockIdx.x >> 3;
    const float* base = xyz + (size_t)b * NN * 3;

    for (int i = tid; i < NN; i += 256) {
        sx[i] = base[3 * i + 0];
        sy[i] = base[3 * i + 1];
        sz[i] = base[3 * i + 2];
    }
    if (tid == 0) {
        MBAR_INIT(smem_u32(&s_mbar[0]), 1);
        MBAR_INIT(smem_u32(&s_mbar[1]), 1);
        MBAR_ARRIVE_EXPECT_TX(smem_u32(&s_mbar[0]), CLUS * 8 * 8);
        MBAR_ARRIVE_EXPECT_TX(smem_u32(&s_mbar[1]), CLUS * 8 * 8);
    }
    __syncthreads();
    CLUSTER_SYNC_();

    unsigned r_slot[2], r_mbar[2];
    if (lane < CLUS) {
#pragma unroll
        for (int p = 0; p < 2; ++p) {
            r_slot[p] = mapa_u32(smem_u32(&s_slots[p][rank * 8 + wid]), (unsigned)lane);
            r_mbar[p] = mapa_u32(smem_u32(&s_mbar[p]), (unsigned)lane);
        }
    }

    const unsigned base_id = rank * 2048u;
    uint64_t px[4], py[4], pz[4];
#pragma unroll
    for (int j = 0; j < 4; ++j) {
        unsigned k = base_id + 2u * ((unsigned)(j << 8) + tid);
        px[j] = *(const uint64_t*)(sx + k);
        py[j] = *(const uint64_t*)(sy + k);
        pz[j] = *(const uint64_t*)(sz + k);
    }
    float dist[8];
#pragma unroll
    for (int i = 0; i < 8; ++i) dist[i] = 1e10f;

    float lx = sx[0], ly = sy[0], lz = sz[0];

    for (int s = 1; s < SS; ++s) {
        const int p = s & 1;
        const int ph = ((s - 1) >> 1) & 1;
        uint64_t ncx = pack2(-lx, -lx);
        uint64_t ncy = pack2(-ly, -ly);
        uint64_t ncz = pack2(-lz, -lz);
#pragma unroll
        for (int j = 0; j < 4; ++j)
            upd(px[j], py[j], pz[j], ncx, ncy, ncz, dist[2 * j], dist[2 * j + 1]);
        float t0 = fmaxf(fmaxf(dist[0], dist[1]), fmaxf(dist[2], dist[3]));
        float t1 = fmaxf(fmaxf(dist[4], dist[5]), fmaxf(dist[6], dist[7]));
        float tm = fmaxf(t0, t1);

        unsigned cand = 0u;
#pragma unroll
        for (int j = 0; j < 4; ++j) {
            unsigned id0 = base_id + 2u * ((unsigned)(j << 8) + tid);
            if (dist[2 * j]     == tm) cand = max(cand, ~id0);
            if (dist[2 * j + 1] == tm) cand = max(cand, ~(id0 + 1u));
        }
        unsigned tmu = __float_as_uint(tm);
        unsigned wmu = __reduce_max_sync(0xffffffffu, tmu);
        cand = __reduce_max_sync(0xffffffffu, (tmu == wmu) ? cand : 0u);
        unsigned long long wkey = ((unsigned long long)wmu << 32) | cand;

        if (lane < CLUS)
            ST_ASYNC_U64(r_slot[p], wkey, r_mbar[p]);

        if (rank == 0 && tid == 0) {
            size_t o3 = (size_t)(b * SS + (s - 1)) * 3;
            g_centers[o3] = lx; g_centers[o3 + 1] = ly; g_centers[o3 + 2] = lz;
            out[OUT_XYZ + o3] = lx; out[OUT_XYZ + o3 + 1] = ly; out[OUT_XYZ + o3 + 2] = lz;
        }

        MBAR_WAIT_PARITY_CLUSTER(smem_u32(&s_mbar[p]), ph);
        if (tid == 0)
            MBAR_ARRIVE_EXPECT_TX(smem_u32(&s_mbar[p]), CLUS * 8 * 8);

        unsigned long long k1 = s_slots[p][lane];
        unsigned long long k2 = s_slots[p][lane + 32];
        unsigned long long k = (k1 > k2) ? k1 : k2;
        unsigned hi = (unsigned)(k >> 32);
        unsigned g2 = __reduce_max_sync(0xffffffffu, hi);
        unsigned m2 = __reduce_max_sync(0xffffffffu, (hi == g2) ? (unsigned)k : 0u);
        unsigned w = ~m2;
        lx = sx[w]; ly = sy[w]; lz = sz[w];
    }
    if (rank == 0 && tid == 0) {
        size_t o3 = (size_t)(b * SS + (SS - 1)) * 3;
        g_centers[o3] = lx; g_centers[o3 + 1] = ly; g_centers[o3 + 2] = lz;
        out[OUT_XYZ + o3] = lx; out[OUT_XYZ + o3 + 1] = ly; out[OUT_XYZ + o3 + 2] = lz;
    }
    CLUSTER_SYNC_();
}

// ---------------------------------------------------------------------------
// Kernel 2: exact KNN top-16, TWO queries per warp (halves SMEM traffic).
// Both sorted lists live in lanes 0..15 (separate register sets).  One
// LDS.128 candidate load feeds two distance computations.  Per query the
// candidate processing order is unchanged (ascending groups, ascending lane
// within group), so the `d < thd` tie shortcut remains valid and the final
// top-16 under the (d, idx) total order is identical to R16.
// 512 threads = 16 warps = 32 queries per CTA; 512 CTAs.
// ---------------------------------------------------------------------------
__global__ __launch_bounds__(512, 2) void knn_kernel(
    const float* __restrict__ xyz, float* __restrict__ out)
{
    __shared__ float4 tile[2048];
    const int tid = threadIdx.x;
    const int w = tid >> 5, lane = tid & 31;
    const int b = blockIdx.x >> 7;
    const int s0 = ((blockIdx.x & 127) << 5) + 2 * w;   // this warp: queries s0, s0+1

    size_t co = (size_t)(b * SS + s0) * 3;
    float qx0 = g_centers[co],     qy0 = g_centers[co + 1], qz0 = g_centers[co + 2];
    float qx1 = g_centers[co + 3], qy1 = g_centers[co + 4], qz1 = g_centers[co + 5];
    float qn0 = __fadd_rn(__fadd_rn(__fmul_rn(qx0, qx0), __fmul_rn(qy0, qy0)),
                          __fmul_rn(qz0, qz0));
    float qn1 = __fadd_rn(__fadd_rn(__fmul_rn(qx1, qx1), __fmul_rn(qy1, qy1)),
                          __fmul_rn(qz1, qz1));

    float ld0 = finf(); int li0 = 0x7FFFFFFF;   // list 0, lanes 0..15
    float ld1 = finf(); int li1 = 0x7FFFFFFF;   // list 1, lanes 0..15
    float thd0 = finf(), thd1 = finf();

    const float* base = xyz + (size_t)b * NN * 3;
    for (int t = 0; t < NN; t += 2048) {
        __syncthreads();
#pragma unroll
        for (int r = 0; r < 4; ++r) {
            int j = t + (r << 9) + tid;
            float x = base[3 * j], y = base[3 * j + 1], z = base[3 * j + 2];
            float nc = __fadd_rn(__fadd_rn(__fmul_rn(x, x), __fmul_rn(y, y)),
                                 __fmul_rn(z, z));
            tile[(r << 9) + tid] = make_float4(x, y, z, nc);
        }
        __syncthreads();
        for (int c = 0; c < 2048; c += 32) {
            float4 cd = tile[c + lane];
            int gi = t + c + lane;
            float dot0 = fmaf(cd.z, qz0, fmaf(cd.y, qy0, __fmul_rn(cd.x, qx0)));
            float d0 = __fsub_rn(__fadd_rn(qn0, cd.w), __fmul_rn(2.0f, dot0));
            float dot1 = fmaf(cd.z, qz1, fmaf(cd.y, qy1, __fmul_rn(cd.x, qx1)));
            float d1 = __fsub_rn(__fadd_rn(qn1, cd.w), __fmul_rn(2.0f, dot1));

            unsigned mask0 = __ballot_sync(0xffffffffu, d0 < thd0);
            if (mask0) {
                do {
                    int l = __ffs(mask0) - 1; mask0 &= mask0 - 1;
                    float dc = __shfl_sync(0xffffffffu, d0, l);
                    int ic = __shfl_sync(0xffffffffu, gi, l);
                    bool lt = (lane < 16) && ((ld0 < dc) || (ld0 == dc && li0 < ic));
                    int r = __popc(__ballot_sync(0xffffffffu, lt));
                    float ud = __shfl_up_sync(0xffffffffu, ld0, 1);
                    int ui = __shfl_up_sync(0xffffffffu, li0, 1);
                    if (lane < 16 && lane >= r) {
                        if (lane == r) { ld0 = dc; li0 = ic; }
                        else { ld0 = ud; li0 = ui; }
                    }
                } while (mask0);
                thd0 = __shfl_sync(0xffffffffu, ld0, 15);
            }
            unsigned mask1 = __ballot_sync(0xffffffffu, d1 < thd1);
            if (mask1) {
                do {
                    int l = __ffs(mask1) - 1; mask1 &= mask1 - 1;
                    float dc = __shfl_sync(0xffffffffu, d1, l);
                    int ic = __shfl_sync(0xffffffffu, gi, l);
                    bool lt = (lane < 16) && ((ld1 < dc) || (ld1 == dc && li1 < ic));
                    int r = __popc(__ballot_sync(0xffffffffu, lt));
                    float ud = __shfl_up_sync(0xffffffffu, ld1, 1);
                    int ui = __shfl_up_sync(0xffffffffu, li1, 1);
                    if (lane < 16 && lane >= r) {
                        if (lane == r) { ld1 = dc; li1 = ic; }
                        else { ld1 = ud; li1 = ui; }
                    }
                } while (mask1);
                thd1 = __shfl_sync(0xffffffffu, ld1, 15);
            }
        }
    }
    if (lane < KK) {
        size_t o = (size_t)(b * SS + s0) * KK + lane;
        g_knn[o] = li0;
        out[OUT_IDX + o] = (float)li0;
        g_knn[o + KK] = li1;
        out[OUT_IDX + o + KK] = (float)li1;
    }
}

// ---------------------------------------------------------------------------
// Kernel 3: rel/planes/max_k, x = planes @ w_shapes^T, BN + ReLU,
// transposed coalesced store to shapes[b][q][s]. Warp per query. (Unchanged.)
// ---------------------------------------------------------------------------
__global__ __launch_bounds__(1024, 1) void feat_kernel(
    const float* __restrict__ xyz,
    const float* __restrict__ wPlanes, const float* __restrict__ wShapes,
    const float* __restrict__ gamma, const float* __restrict__ beta,
    const float* __restrict__ mean, const float* __restrict__ var,
    float* __restrict__ out)
{
    extern __shared__ float fsm[];
    float* s_ws    = fsm;                  // 128*65
    float* s_wp    = s_ws + QQ * 65;       // 192
    float* s_scale = s_wp + 192;           // 128
    float* s_beta  = s_scale + QQ;         // 128
    float* s_mean  = s_beta + QQ;          // 128
    float* s_pl    = s_mean + QQ;          // 32*64
    float* s_xb    = s_pl + 32 * 64;       // 128*33

    const int tid = threadIdx.x;
    for (int i = tid; i < QQ * PP; i += 1024)
        s_ws[(i >> 6) * 65 + (i & 63)] = wShapes[i];
    for (int i = tid; i < PP * 3; i += 1024) s_wp[i] = wPlanes[i];
    if (tid < QQ) {
        s_scale[tid] = gamma[tid] / sqrtf(var[tid] + 1e-5f);
        s_beta[tid] = beta[tid];
        s_mean[tid] = mean[tid];
    }
    __syncthreads();

    const int w = tid >> 5, lane = tid & 31;
    const int b = blockIdx.x >> 7;
    const int s0 = (blockIdx.x & 127) << 5;
    const int s = s0 + w;

    size_t co = (size_t)(b * SS + s) * 3;
    float cx = g_centers[co], cy = g_centers[co + 1], cz = g_centers[co + 2];

    float rx = 0.f, ry = 0.f, rz = 0.f, nr = 1.f;
    if (lane >= 1 && lane < 16) {
        int j = g_knn[(size_t)(b * SS + s) * KK + lane];
        const float* p = xyz + ((size_t)b * NN + j) * 3;
        rx = __fsub_rn(p[0], cx); ry = __fsub_rn(p[1], cy); rz = __fsub_rn(p[2], cz);
        nr = __fadd_rn(sqrtf(__fadd_rn(__fadd_rn(__fmul_rn(rx, rx), __fmul_rn(ry, ry)),
                                       __fmul_rn(rz, rz))), 1e-8f);
    }
    float w0x = s_wp[lane * 3], w0y = s_wp[lane * 3 + 1], w0z = s_wp[lane * 3 + 2];
    float w1x = s_wp[(lane + 32) * 3], w1y = s_wp[(lane + 32) * 3 + 1],
          w1z = s_wp[(lane + 32) * 3 + 2];
    float acc0 = -finf(), acc1 = -finf();
#pragma unroll
    for (int k = 1; k < 16; ++k) {
        float bx = __shfl_sync(0xffffffffu, rx, k);
        float by = __shfl_sync(0xffffffffu, ry, k);
        float bz = __shfl_sync(0xffffffffu, rz, k);
        float bn = __shfl_sync(0xffffffffu, nr, k);
        float d0 = fmaf(bz, w0z, fmaf(by, w0y, __fmul_rn(bx, w0x)));
        float v0 = __fdiv_rn(d0, bn);
        acc0 = fmaxf(acc0, __fmul_rn(__fmul_rn(bn, v0), fabsf(v0)));
        float d1 = fmaf(bz, w1z, fmaf(by, w1y, __fmul_rn(bx, w1x)));
        float v1 = __fdiv_rn(d1, bn);
        acc1 = fmaxf(acc1, __fmul_rn(__fmul_rn(bn, v1), fabsf(v1)));
    }
    s_pl[w * 64 + lane] = acc0;
    s_pl[w * 64 + 32 + lane] = acc1;
    __syncwarp();

#pragma unroll
    for (int j = 0; j < 4; ++j) {
        int q = lane + 32 * j;
        float acc = 0.0f;
#pragma unroll 16
        for (int p = 0; p < PP; ++p)
            acc = fmaf(s_pl[w * 64 + p], s_ws[q * 65 + p], acc);
        float x = __fadd_rn(__fmul_rn(__fsub_rn(acc, s_mean[q]), s_scale[q]), s_beta[q]);
        s_xb[q * 33 + w] = fmaxf(x, 0.0f);
    }
    __syncthreads();

    for (int i = tid; i < QQ * 32; i += 1024) {
        int q = i >> 5, sl = i & 31;
        out[OUT_SHAPES + ((size_t)(b * QQ + q)) * SS + s0 + sl] = s_xb[q * 33 + sl];
    }
}

extern "C" void kernel_launch(void* const* d_in, const int* in_sizes, int n_in,
                              void* d_out, int out_size) {
    const float* xyz     = (const float*)d_in[0];
    const float* wPlanes = (const float*)d_in[1];
    const float* wShapes = (const float*)d_in[2];
    const float* gamma   = (const float*)d_in[3];
    const float* beta    = (const float*)d_in[4];
    const float* mean    = (const float*)d_in[5];
    const float* var     = (const float*)d_in[6];
    float* out = (float*)d_out;

    cudaFuncSetAttribute(fps_kernel, cudaFuncAttributeMaxDynamicSharedMemorySize,
                         3 * NN * sizeof(float));
    cudaFuncSetAttribute(feat_kernel, cudaFuncAttributeMaxDynamicSharedMemorySize,
                         (QQ * 65 + 192 + 3 * QQ + 32 * 64 + QQ * 33) * (int)sizeof(float));

    fps_kernel<<<BB * CLUS, 256, 3 * NN * sizeof(float)>>>(xyz, out);
    knn_kernel<<<BB * 128, 512>>>(xyz, out);
    feat_kernel<<<BB * 128, 1024,
                  (QQ * 65 + 192 + 3 * QQ + 32 * 64 + QQ * 33) * sizeof(float)>>>(
        xyz, wPlanes, wShapes, gamma, beta, mean, var, out);
}